// round 1
// baseline (speedup 1.0000x reference)
#include <cuda_runtime.h>
#include <math.h>

#define BSZ   8
#define TLEN  2048
#define CDIM  1024
#define DDIM  1024
#define MTOT  (BSZ * TLEN)   // 16384

// ---------------- scratch (static device globals; no allocs allowed) ----------
__device__ float g_xk[MTOT * CDIM];
__device__ float g_xv[MTOT * CDIM];
__device__ float g_xr[MTOT * CDIM];
__device__ float g_k [MTOT * DDIM];
__device__ float g_v [MTOT * DDIM];
__device__ float g_r [MTOT * DDIM];   // sigmoid(r) stored
__device__ float g_rwkv[MTOT * DDIM];

// ---------------- 1. time-shift + mixing --------------------------------------
__global__ void mix_kernel(const float* __restrict__ x,
                           const float* __restrict__ tmk,
                           const float* __restrict__ tmv,
                           const float* __restrict__ tmr)
{
    int idx = blockIdx.x * blockDim.x + threadIdx.x;     // over MTOT * CDIM / 4
    const int c4cnt = CDIM / 4;
    int c4 = idx % c4cnt;
    int m  = idx / c4cnt;
    int t  = m % TLEN;

    float4 xv4 = reinterpret_cast<const float4*>(x)[idx];
    float4 xx4 = (t > 0) ? reinterpret_cast<const float4*>(x)[idx - c4cnt]
                         : make_float4(0.f, 0.f, 0.f, 0.f);
    float4 mk = reinterpret_cast<const float4*>(tmk)[c4];
    float4 mv = reinterpret_cast<const float4*>(tmv)[c4];
    float4 mr = reinterpret_cast<const float4*>(tmr)[c4];

    float4 ok, ov, orr;
    ok.x = xv4.x * mk.x + xx4.x * (1.f - mk.x);
    ok.y = xv4.y * mk.y + xx4.y * (1.f - mk.y);
    ok.z = xv4.z * mk.z + xx4.z * (1.f - mk.z);
    ok.w = xv4.w * mk.w + xx4.w * (1.f - mk.w);
    ov.x = xv4.x * mv.x + xx4.x * (1.f - mv.x);
    ov.y = xv4.y * mv.y + xx4.y * (1.f - mv.y);
    ov.z = xv4.z * mv.z + xx4.z * (1.f - mv.z);
    ov.w = xv4.w * mv.w + xx4.w * (1.f - mv.w);
    orr.x = xv4.x * mr.x + xx4.x * (1.f - mr.x);
    orr.y = xv4.y * mr.y + xx4.y * (1.f - mr.y);
    orr.z = xv4.z * mr.z + xx4.z * (1.f - mr.z);
    orr.w = xv4.w * mr.w + xx4.w * (1.f - mr.w);

    reinterpret_cast<float4*>(g_xk)[idx] = ok;
    reinterpret_cast<float4*>(g_xv)[idx] = ov;
    reinterpret_cast<float4*>(g_xr)[idx] = orr;
}

// ---------------- 2. fp32 tiled GEMM:  C[M,N] = A[M,K] * B[N,K]^T -------------
#define BM 128
#define BN 128
#define BK 16

__global__ __launch_bounds__(256, 2)
void gemm_tn(const float* __restrict__ A, const float* __restrict__ Bm,
             float* __restrict__ C, int M, int N, int K, int act)
{
    __shared__ float As[BK][BM + 4];
    __shared__ float Bs[BK][BN + 4];

    int tid = threadIdx.x;
    int bx = blockIdx.x, by = blockIdx.y;
    int tx = tid & 15, ty = tid >> 4;

    int loadRow = tid >> 1;            // 0..127
    int loadK   = (tid & 1) * 8;       // 0 or 8

    const float* Aptr = A + (size_t)(by * BM + loadRow) * K + loadK;
    const float* Bptr = Bm + (size_t)(bx * BN + loadRow) * K + loadK;

    float acc[8][8];
    #pragma unroll
    for (int i = 0; i < 8; i++)
        #pragma unroll
        for (int j = 0; j < 8; j++) acc[i][j] = 0.f;

    for (int k0 = 0; k0 < K; k0 += BK) {
        float4 a0 = *reinterpret_cast<const float4*>(Aptr + k0);
        float4 a1 = *reinterpret_cast<const float4*>(Aptr + k0 + 4);
        float4 b0 = *reinterpret_cast<const float4*>(Bptr + k0);
        float4 b1 = *reinterpret_cast<const float4*>(Bptr + k0 + 4);

        __syncthreads();
        As[loadK + 0][loadRow] = a0.x;
        As[loadK + 1][loadRow] = a0.y;
        As[loadK + 2][loadRow] = a0.z;
        As[loadK + 3][loadRow] = a0.w;
        As[loadK + 4][loadRow] = a1.x;
        As[loadK + 5][loadRow] = a1.y;
        As[loadK + 6][loadRow] = a1.z;
        As[loadK + 7][loadRow] = a1.w;
        Bs[loadK + 0][loadRow] = b0.x;
        Bs[loadK + 1][loadRow] = b0.y;
        Bs[loadK + 2][loadRow] = b0.z;
        Bs[loadK + 3][loadRow] = b0.w;
        Bs[loadK + 4][loadRow] = b1.x;
        Bs[loadK + 5][loadRow] = b1.y;
        Bs[loadK + 6][loadRow] = b1.z;
        Bs[loadK + 7][loadRow] = b1.w;
        __syncthreads();

        #pragma unroll
        for (int kk = 0; kk < BK; kk++) {
            float a[8], b[8];
            *reinterpret_cast<float4*>(a)     = *reinterpret_cast<const float4*>(&As[kk][ty * 8]);
            *reinterpret_cast<float4*>(a + 4) = *reinterpret_cast<const float4*>(&As[kk][ty * 8 + 4]);
            *reinterpret_cast<float4*>(b)     = *reinterpret_cast<const float4*>(&Bs[kk][tx * 8]);
            *reinterpret_cast<float4*>(b + 4) = *reinterpret_cast<const float4*>(&Bs[kk][tx * 8 + 4]);
            #pragma unroll
            for (int i = 0; i < 8; i++)
                #pragma unroll
                for (int j = 0; j < 8; j++)
                    acc[i][j] = fmaf(a[i], b[j], acc[i][j]);
        }
    }

    #pragma unroll
    for (int i = 0; i < 8; i++) {
        float* Crow = C + (size_t)(by * BM + ty * 8 + i) * N + bx * BN + tx * 8;
        float vals[8];
        #pragma unroll
        for (int j = 0; j < 8; j++) {
            float vv = acc[i][j];
            if (act) vv = 1.f / (1.f + expf(-vv));
            vals[j] = vv;
        }
        *reinterpret_cast<float4*>(Crow)     = *reinterpret_cast<float4*>(vals);
        *reinterpret_cast<float4*>(Crow + 4) = *reinterpret_cast<float4*>(vals + 4);
    }
}

// ---------------- 3. wkv scan + gating ----------------------------------------
#define WKV_U 16
__global__ void wkv_kernel(const float* __restrict__ time_decay,
                           const float* __restrict__ time_first)
{
    int idx = blockIdx.x * blockDim.x + threadIdx.x;   // over BSZ*DDIM
    int b = idx / DDIM;
    int d = idx % DDIM;

    float ew = expf(-expf(time_decay[d]));
    float eu = expf(time_first[d]);

    const float* kp = g_k + (size_t)b * TLEN * DDIM + d;
    const float* vp = g_v + (size_t)b * TLEN * DDIM + d;
    const float* rp = g_r + (size_t)b * TLEN * DDIM + d;
    float*       op = g_rwkv + (size_t)b * TLEN * DDIM + d;

    float aa = 0.f, bb = 0.f;

    for (int t0 = 0; t0 < TLEN; t0 += WKV_U) {
        float kk[WKV_U], vv[WKV_U], rr[WKV_U];
        #pragma unroll
        for (int i = 0; i < WKV_U; i++) {
            kk[i] = kp[(size_t)(t0 + i) * DDIM];
            vv[i] = vp[(size_t)(t0 + i) * DDIM];
            rr[i] = rp[(size_t)(t0 + i) * DDIM];
        }
        #pragma unroll
        for (int i = 0; i < WKV_U; i++) {
            float ek  = expf(kk[i]);
            float ekv = ek * vv[i];
            float out = (eu * ekv + aa) / (eu * ek + bb);
            op[(size_t)(t0 + i) * DDIM] = rr[i] * out;
            aa = ew * aa + ekv;
            bb = ew * bb + ek;
        }
    }
}

// ---------------- launch ------------------------------------------------------
extern "C" void kernel_launch(void* const* d_in, const int* in_sizes, int n_in,
                              void* d_out, int out_size)
{
    const float* x    = (const float*)d_in[0];
    const float* td   = (const float*)d_in[1];
    const float* tf   = (const float*)d_in[2];
    const float* tmk  = (const float*)d_in[3];
    const float* tmv  = (const float*)d_in[4];
    const float* tmr  = (const float*)d_in[5];
    const float* Wk   = (const float*)d_in[6];
    const float* Wv   = (const float*)d_in[7];
    const float* Wr   = (const float*)d_in[8];
    const float* Wo   = (const float*)d_in[9];
    float* out = (float*)d_out;

    float *p_xk, *p_xv, *p_xr, *p_k, *p_v, *p_r, *p_rwkv;
    cudaGetSymbolAddress((void**)&p_xk, g_xk);
    cudaGetSymbolAddress((void**)&p_xv, g_xv);
    cudaGetSymbolAddress((void**)&p_xr, g_xr);
    cudaGetSymbolAddress((void**)&p_k,  g_k);
    cudaGetSymbolAddress((void**)&p_v,  g_v);
    cudaGetSymbolAddress((void**)&p_r,  g_r);
    cudaGetSymbolAddress((void**)&p_rwkv, g_rwkv);

    // 1. mixing
    {
        int n = MTOT * CDIM / 4;
        mix_kernel<<<n / 256, 256>>>(x, tmk, tmv, tmr);
    }

    // 2. projections: [16384,1024] x [1024,1024]^T
    dim3 grid(CDIM / BN, MTOT / BM);
    gemm_tn<<<grid, 256>>>(p_xk, Wk, p_k, MTOT, DDIM, CDIM, 0);
    gemm_tn<<<grid, 256>>>(p_xv, Wv, p_v, MTOT, DDIM, CDIM, 0);
    gemm_tn<<<grid, 256>>>(p_xr, Wr, p_r, MTOT, DDIM, CDIM, 1);  // sigmoid

    // 3. wkv scan (+ gate by sigmoid(r))
    wkv_kernel<<<(BSZ * DDIM) / 256, 256>>>(td, tf);

    // 4. output projection: out[m,c] = sum_d rwkv[m,d] * Wo[c,d]
    gemm_tn<<<grid, 256>>>(p_rwkv, Wo, out, MTOT, CDIM, DDIM, 0);
}

// round 4
// speedup vs baseline: 3.4759x; 3.4759x over previous
#include <cuda_runtime.h>
#include <math.h>
#include <stdint.h>

#define BSZ   8
#define TLEN  2048
#define CDIM  1024
#define DDIM  1024
#define MTOT  (BSZ * TLEN)   // 16384

// ---------------- scratch (static device globals; no allocs allowed) ----------
__device__ __align__(256) float g_xk[MTOT * CDIM];
__device__ __align__(256) float g_xv[MTOT * CDIM];
__device__ __align__(256) float g_xr[MTOT * CDIM];
__device__ __align__(256) float g_k [MTOT * DDIM];
__device__ __align__(256) float g_v [MTOT * DDIM];
__device__ __align__(256) float g_r [MTOT * DDIM];   // sigmoid(r)
__device__ __align__(256) float g_rwkv[MTOT * DDIM];
__device__ __align__(256) float g_Wk[DDIM * CDIM];
__device__ __align__(256) float g_Wv[DDIM * CDIM];
__device__ __align__(256) float g_Wr[DDIM * CDIM];
__device__ __align__(256) float g_Wo[CDIM * DDIM];

// ---------------- tf32 helpers ------------------------------------------------
__device__ __forceinline__ float tf32r(float x) {
    uint32_t u;
    asm("cvt.rna.tf32.f32 %0, %1;" : "=r"(u) : "f"(x));
    return __uint_as_float(u);
}

__device__ __forceinline__ void mma_m16n8k8(float c[4], const uint32_t a[4],
                                            const uint32_t b[2]) {
    asm volatile(
        "mma.sync.aligned.m16n8k8.row.col.f32.tf32.tf32.f32 "
        "{%0,%1,%2,%3}, {%4,%5,%6,%7}, {%8,%9}, {%0,%1,%2,%3};"
        : "+f"(c[0]), "+f"(c[1]), "+f"(c[2]), "+f"(c[3])
        : "r"(a[0]), "r"(a[1]), "r"(a[2]), "r"(a[3]), "r"(b[0]), "r"(b[1]));
}

__device__ __forceinline__ void cp_async16(uint32_t dst, const void* src) {
    asm volatile("cp.async.cg.shared.global [%0], [%1], 16;" ::"r"(dst), "l"(src));
}

// ---------------- 0. round weights to tf32 ------------------------------------
__global__ void round_tf32_k(const float* __restrict__ s, float* __restrict__ d, int n4) {
    int i = blockIdx.x * blockDim.x + threadIdx.x;
    if (i < n4) {
        float4 v = reinterpret_cast<const float4*>(s)[i];
        v.x = tf32r(v.x); v.y = tf32r(v.y); v.z = tf32r(v.z); v.w = tf32r(v.w);
        reinterpret_cast<float4*>(d)[i] = v;
    }
}

// ---------------- 1. time-shift + mixing (outputs tf32-rounded) ---------------
__global__ void mix_kernel(const float* __restrict__ x,
                           const float* __restrict__ tmk,
                           const float* __restrict__ tmv,
                           const float* __restrict__ tmr)
{
    int idx = blockIdx.x * blockDim.x + threadIdx.x;     // over MTOT * CDIM / 4
    const int c4cnt = CDIM / 4;
    int c4 = idx % c4cnt;
    int m  = idx / c4cnt;
    int t  = m % TLEN;

    float4 xv4 = reinterpret_cast<const float4*>(x)[idx];
    float4 xx4 = (t > 0) ? reinterpret_cast<const float4*>(x)[idx - c4cnt]
                         : make_float4(0.f, 0.f, 0.f, 0.f);
    float4 mk = reinterpret_cast<const float4*>(tmk)[c4];
    float4 mv = reinterpret_cast<const float4*>(tmv)[c4];
    float4 mr = reinterpret_cast<const float4*>(tmr)[c4];

    float4 ok, ov, orr;
    ok.x = tf32r(xv4.x * mk.x + xx4.x * (1.f - mk.x));
    ok.y = tf32r(xv4.y * mk.y + xx4.y * (1.f - mk.y));
    ok.z = tf32r(xv4.z * mk.z + xx4.z * (1.f - mk.z));
    ok.w = tf32r(xv4.w * mk.w + xx4.w * (1.f - mk.w));
    ov.x = tf32r(xv4.x * mv.x + xx4.x * (1.f - mv.x));
    ov.y = tf32r(xv4.y * mv.y + xx4.y * (1.f - mv.y));
    ov.z = tf32r(xv4.z * mv.z + xx4.z * (1.f - mv.z));
    ov.w = tf32r(xv4.w * mv.w + xx4.w * (1.f - mv.w));
    orr.x = tf32r(xv4.x * mr.x + xx4.x * (1.f - mr.x));
    orr.y = tf32r(xv4.y * mr.y + xx4.y * (1.f - mr.y));
    orr.z = tf32r(xv4.z * mr.z + xx4.z * (1.f - mr.z));
    orr.w = tf32r(xv4.w * mr.w + xx4.w * (1.f - mr.w));

    reinterpret_cast<float4*>(g_xk)[idx] = ok;
    reinterpret_cast<float4*>(g_xv)[idx] = ov;
    reinterpret_cast<float4*>(g_xr)[idx] = orr;
}

// ---------------- 2. tf32 tensor-core GEMM:  C[M,N] = A[M,K] * B[N,K]^T -------
// 128x128x32 block tile, 4 warps (64x64 each), 2-stage cp.async pipeline,
// XOR-swizzled smem (conflict-free scalar fragment loads).
#define SWIZ(m, k) (((m) << 5) + (((((k) >> 2) ^ ((m) & 7))) << 2) + ((k) & 3))
#define STAGE_F 8192   // floats per stage: A 128*32 + B 128*32

__global__ __launch_bounds__(128)
void gemm_tf32(const float* __restrict__ A, const float* __restrict__ B,
               float* __restrict__ C, int M, int N, int K, int act)
{
    extern __shared__ float sm[];
    const int tid  = threadIdx.x;
    const int lane = tid & 31;
    const int wid  = tid >> 5;
    const int wm = (wid >> 1) << 6;     // 0 or 64
    const int wn = (wid & 1) << 6;      // 0 or 64
    const int g  = lane >> 2;           // groupID 0..7
    const int tg = lane & 3;            // thread-in-group 0..3

    // global->smem load mapping: thread owns k-chunk kc of rows m0, m0+16, ...
    const int kc = tid & 7;             // 16B chunk in K (0..7)
    const int m0 = tid >> 3;            // 0..15
    const int dc = kc ^ (m0 & 7);       // swizzled chunk

    // FIX (R2 bug): global pointers must include the per-thread row offset m0.
    const float* Ag = A + ((((size_t)blockIdx.y) << 7) + m0) * K + (size_t)kc * 4;
    const float* Bg = B + ((((size_t)blockIdx.x) << 7) + m0) * K + (size_t)kc * 4;

    uint32_t sbase = (uint32_t)__cvta_generic_to_shared(sm);
    uint32_t dA = sbase + (uint32_t)(((m0 << 5) + (dc << 2)) << 2);
    uint32_t dB = dA + (4096u << 2);

    float acc[4][8][4];
    #pragma unroll
    for (int i = 0; i < 4; i++)
        #pragma unroll
        for (int j = 0; j < 8; j++)
            #pragma unroll
            for (int l = 0; l < 4; l++) acc[i][j][l] = 0.f;

    const int kIters = K >> 5;

#define ISSUE(IT, S)                                                          \
    {                                                                         \
        uint32_t offS = (uint32_t)((S) * (STAGE_F * 4));                      \
        const float* ap = Ag + (size_t)(IT) * 32;                             \
        const float* bp = Bg + (size_t)(IT) * 32;                             \
        _Pragma("unroll")                                                     \
        for (int j = 0; j < 8; j++) {                                         \
            cp_async16(dA + offS + (uint32_t)(j * 2048),                      \
                       ap + (size_t)(j << 4) * K);                            \
            cp_async16(dB + offS + (uint32_t)(j * 2048),                      \
                       bp + (size_t)(j << 4) * K);                            \
        }                                                                     \
        asm volatile("cp.async.commit_group;" ::);                            \
    }

    ISSUE(0, 0);

    for (int it = 0; it < kIters; ++it) {
        if (it + 1 < kIters) {
            ISSUE(it + 1, (it + 1) & 1);
            asm volatile("cp.async.wait_group 1;" ::);
        } else {
            asm volatile("cp.async.wait_group 0;" ::);
        }
        __syncthreads();

        const float* As = sm + (it & 1) * STAGE_F;
        const float* Bs = As + 4096;

        #pragma unroll
        for (int kq = 0; kq < 4; kq++) {
            const int kk = kq << 3;
            uint32_t af[4][4], bf[8][2];
            #pragma unroll
            for (int mi = 0; mi < 4; mi++) {
                int m = wm + (mi << 4) + g;
                int k = kk + tg;
                af[mi][0] = __float_as_uint(As[SWIZ(m, k)]);
                af[mi][1] = __float_as_uint(As[SWIZ(m + 8, k)]);
                af[mi][2] = __float_as_uint(As[SWIZ(m, k + 4)]);
                af[mi][3] = __float_as_uint(As[SWIZ(m + 8, k + 4)]);
            }
            #pragma unroll
            for (int ni = 0; ni < 8; ni++) {
                int n = wn + (ni << 3) + g;
                bf[ni][0] = __float_as_uint(Bs[SWIZ(n, kk + tg)]);
                bf[ni][1] = __float_as_uint(Bs[SWIZ(n, kk + 4 + tg)]);
            }
            #pragma unroll
            for (int mi = 0; mi < 4; mi++)
                #pragma unroll
                for (int ni = 0; ni < 8; ni++)
                    mma_m16n8k8(acc[mi][ni], af[mi], bf[ni]);
        }
        __syncthreads();
    }

    // epilogue
    size_t rowBase = (((size_t)blockIdx.y) << 7) + wm + g;
    int colBase = (blockIdx.x << 7) + wn + (tg << 1);
    #pragma unroll
    for (int mi = 0; mi < 4; mi++) {
        #pragma unroll
        for (int ni = 0; ni < 8; ni++) {
            size_t r0 = rowBase + (mi << 4);
            int col = colBase + (ni << 3);
            float x0 = acc[mi][ni][0], x1 = acc[mi][ni][1];
            float x2 = acc[mi][ni][2], x3 = acc[mi][ni][3];
            if (act) {
                x0 = 1.f / (1.f + expf(-x0));
                x1 = 1.f / (1.f + expf(-x1));
                x2 = 1.f / (1.f + expf(-x2));
                x3 = 1.f / (1.f + expf(-x3));
            }
            *reinterpret_cast<float2*>(C + r0 * N + col)       = make_float2(x0, x1);
            *reinterpret_cast<float2*>(C + (r0 + 8) * N + col) = make_float2(x2, x3);
        }
    }
}

// ---------------- 3. wkv scan + gating ----------------------------------------
#define WKV_U 16
__global__ void wkv_kernel(const float* __restrict__ time_decay,
                           const float* __restrict__ time_first)
{
    int idx = blockIdx.x * blockDim.x + threadIdx.x;   // over BSZ*DDIM
    int b = idx / DDIM;
    int d = idx % DDIM;

    float ew = expf(-expf(time_decay[d]));
    float eu = expf(time_first[d]);

    const float* kp = g_k + (size_t)b * TLEN * DDIM + d;
    const float* vp = g_v + (size_t)b * TLEN * DDIM + d;
    const float* rp = g_r + (size_t)b * TLEN * DDIM + d;
    float*       op = g_rwkv + (size_t)b * TLEN * DDIM + d;

    float aa = 0.f, bb = 0.f;

    for (int t0 = 0; t0 < TLEN; t0 += WKV_U) {
        float kk[WKV_U], vv[WKV_U], rr[WKV_U];
        #pragma unroll
        for (int i = 0; i < WKV_U; i++) {
            kk[i] = kp[(size_t)(t0 + i) * DDIM];
            vv[i] = vp[(size_t)(t0 + i) * DDIM];
            rr[i] = rp[(size_t)(t0 + i) * DDIM];
        }
        #pragma unroll
        for (int i = 0; i < WKV_U; i++) {
            float ek  = expf(kk[i]);
            float ekv = ek * vv[i];
            float out = (eu * ekv + aa) / (eu * ek + bb);
            op[(size_t)(t0 + i) * DDIM] = tf32r(rr[i] * out);
            aa = ew * aa + ekv;
            bb = ew * bb + ek;
        }
    }
}

// ---------------- launch ------------------------------------------------------
extern "C" void kernel_launch(void* const* d_in, const int* in_sizes, int n_in,
                              void* d_out, int out_size)
{
    const float* x    = (const float*)d_in[0];
    const float* td   = (const float*)d_in[1];
    const float* tf   = (const float*)d_in[2];
    const float* tmk  = (const float*)d_in[3];
    const float* tmv  = (const float*)d_in[4];
    const float* tmr  = (const float*)d_in[5];
    const float* Wk   = (const float*)d_in[6];
    const float* Wv   = (const float*)d_in[7];
    const float* Wr   = (const float*)d_in[8];
    const float* Wo   = (const float*)d_in[9];
    float* out = (float*)d_out;

    float *p_xk, *p_xv, *p_xr, *p_k, *p_v, *p_r, *p_rwkv;
    float *p_Wk, *p_Wv, *p_Wr, *p_Wo;
    cudaGetSymbolAddress((void**)&p_xk, g_xk);
    cudaGetSymbolAddress((void**)&p_xv, g_xv);
    cudaGetSymbolAddress((void**)&p_xr, g_xr);
    cudaGetSymbolAddress((void**)&p_k,  g_k);
    cudaGetSymbolAddress((void**)&p_v,  g_v);
    cudaGetSymbolAddress((void**)&p_r,  g_r);
    cudaGetSymbolAddress((void**)&p_rwkv, g_rwkv);
    cudaGetSymbolAddress((void**)&p_Wk, g_Wk);
    cudaGetSymbolAddress((void**)&p_Wv, g_Wv);
    cudaGetSymbolAddress((void**)&p_Wr, g_Wr);
    cudaGetSymbolAddress((void**)&p_Wo, g_Wo);

    cudaFuncSetAttribute(gemm_tf32, cudaFuncAttributeMaxDynamicSharedMemorySize,
                         2 * STAGE_F * 4);

    // 0. round weights to tf32
    {
        int n4 = (DDIM * CDIM) / 4;
        int blk = 256, grd = (n4 + blk - 1) / blk;
        round_tf32_k<<<grd, blk>>>(Wk, p_Wk, n4);
        round_tf32_k<<<grd, blk>>>(Wv, p_Wv, n4);
        round_tf32_k<<<grd, blk>>>(Wr, p_Wr, n4);
        round_tf32_k<<<grd, blk>>>(Wo, p_Wo, n4);
    }

    // 1. mixing (tf32-rounded outputs)
    {
        int n = MTOT * CDIM / 4;
        mix_kernel<<<n / 256, 256>>>(x, tmk, tmv, tmr);
    }

    // 2. projections: [16384,1024] x [1024,1024]^T on tensor cores
    dim3 grid(DDIM / 128, MTOT / 128);
    size_t smem = 2 * STAGE_F * 4;
    gemm_tf32<<<grid, 128, smem>>>(p_xk, p_Wk, p_k, MTOT, DDIM, CDIM, 0);
    gemm_tf32<<<grid, 128, smem>>>(p_xv, p_Wv, p_v, MTOT, DDIM, CDIM, 0);
    gemm_tf32<<<grid, 128, smem>>>(p_xr, p_Wr, p_r, MTOT, DDIM, CDIM, 1);

    // 3. wkv scan (+ gate by sigmoid(r)); 64-thread blocks to cover all SMs
    wkv_kernel<<<(BSZ * DDIM) / 64, 64>>>(td, tf);

    // 4. output projection
    dim3 grid2(CDIM / 128, MTOT / 128);
    gemm_tf32<<<grid2, 128, smem>>>(p_rwkv, p_Wo, out, MTOT, CDIM, DDIM, 0);
}

// round 8
// speedup vs baseline: 3.6747x; 1.0572x over previous
#include <cuda_runtime.h>
#include <math.h>
#include <stdint.h>

#define BSZ   8
#define TLEN  2048
#define CDIM  1024
#define DDIM  1024
#define MTOT  (BSZ * TLEN)   // 16384

// ---------------- scratch (static device globals; no allocs allowed) ----------
__device__ __align__(256) float g_xk[MTOT * CDIM];
__device__ __align__(256) float g_xv[MTOT * CDIM];
__device__ __align__(256) float g_xr[MTOT * CDIM];
__device__ __align__(256) float g_k [MTOT * DDIM];
__device__ __align__(256) float g_v [MTOT * DDIM];
__device__ __align__(256) float g_r [MTOT * DDIM];   // sigmoid(r)
__device__ __align__(256) float g_rwkv[MTOT * DDIM];
__device__ __align__(256) float g_Wk[DDIM * CDIM];
__device__ __align__(256) float g_Wv[DDIM * CDIM];
__device__ __align__(256) float g_Wr[DDIM * CDIM];
__device__ __align__(256) float g_Wo[CDIM * DDIM];

// ---------------- tf32 helpers ------------------------------------------------
__device__ __forceinline__ float tf32r(float x) {
    uint32_t u;
    asm("cvt.rna.tf32.f32 %0, %1;" : "=r"(u) : "f"(x));
    return __uint_as_float(u);
}

__device__ __forceinline__ void mma_m16n8k8(float c[4], const uint32_t a[4],
                                            uint32_t b0, uint32_t b1) {
    asm volatile(
        "mma.sync.aligned.m16n8k8.row.col.f32.tf32.tf32.f32 "
        "{%0,%1,%2,%3}, {%4,%5,%6,%7}, {%8,%9}, {%0,%1,%2,%3};"
        : "+f"(c[0]), "+f"(c[1]), "+f"(c[2]), "+f"(c[3])
        : "r"(a[0]), "r"(a[1]), "r"(a[2]), "r"(a[3]), "r"(b0), "r"(b1));
}

__device__ __forceinline__ void cp_async16(uint32_t dst, const void* src) {
    asm volatile("cp.async.cg.shared.global [%0], [%1], 16;" ::"r"(dst), "l"(src));
}

__device__ __forceinline__ void ldsm_x4(uint32_t& r0, uint32_t& r1,
                                        uint32_t& r2, uint32_t& r3, uint32_t addr) {
    asm volatile("ldmatrix.sync.aligned.m8n8.x4.shared.b16 {%0,%1,%2,%3}, [%4];"
                 : "=r"(r0), "=r"(r1), "=r"(r2), "=r"(r3) : "r"(addr));
}

// ---------------- 0. round all four weight matrices to tf32 -------------------
__global__ void round_weights(const float* __restrict__ wk, const float* __restrict__ wv,
                              const float* __restrict__ wr, const float* __restrict__ wo)
{
    const int per = (DDIM * CDIM) / 4;        // float4s per weight
    int i = blockIdx.x * blockDim.x + threadIdx.x;
    int sel = i / per;
    int off = i - sel * per;
    const float* s = (sel == 0) ? wk : (sel == 1) ? wv : (sel == 2) ? wr : wo;
    float* d = (sel == 0) ? g_Wk : (sel == 1) ? g_Wv : (sel == 2) ? g_Wr : g_Wo;
    float4 v = reinterpret_cast<const float4*>(s)[off];
    v.x = tf32r(v.x); v.y = tf32r(v.y); v.z = tf32r(v.z); v.w = tf32r(v.w);
    reinterpret_cast<float4*>(d)[off] = v;
}

// ---------------- 1. time-shift + mixing (outputs tf32-rounded) ---------------
__global__ void mix_kernel(const float* __restrict__ x,
                           const float* __restrict__ tmk,
                           const float* __restrict__ tmv,
                           const float* __restrict__ tmr)
{
    int idx = blockIdx.x * blockDim.x + threadIdx.x;     // over MTOT * CDIM / 4
    const int c4cnt = CDIM / 4;
    int c4 = idx % c4cnt;
    int m  = idx / c4cnt;
    int t  = m % TLEN;

    float4 xv4 = reinterpret_cast<const float4*>(x)[idx];
    float4 xx4 = (t > 0) ? reinterpret_cast<const float4*>(x)[idx - c4cnt]
                         : make_float4(0.f, 0.f, 0.f, 0.f);
    float4 mk = reinterpret_cast<const float4*>(tmk)[c4];
    float4 mv = reinterpret_cast<const float4*>(tmv)[c4];
    float4 mr = reinterpret_cast<const float4*>(tmr)[c4];

    float4 ok, ov, orr;
    ok.x = tf32r(xv4.x * mk.x + xx4.x * (1.f - mk.x));
    ok.y = tf32r(xv4.y * mk.y + xx4.y * (1.f - mk.y));
    ok.z = tf32r(xv4.z * mk.z + xx4.z * (1.f - mk.z));
    ok.w = tf32r(xv4.w * mk.w + xx4.w * (1.f - mk.w));
    ov.x = tf32r(xv4.x * mv.x + xx4.x * (1.f - mv.x));
    ov.y = tf32r(xv4.y * mv.y + xx4.y * (1.f - mv.y));
    ov.z = tf32r(xv4.z * mv.z + xx4.z * (1.f - mv.z));
    ov.w = tf32r(xv4.w * mv.w + xx4.w * (1.f - mv.w));
    orr.x = tf32r(xv4.x * mr.x + xx4.x * (1.f - mr.x));
    orr.y = tf32r(xv4.y * mr.y + xx4.y * (1.f - mr.y));
    orr.z = tf32r(xv4.z * mr.z + xx4.z * (1.f - mr.z));
    orr.w = tf32r(xv4.w * mr.w + xx4.w * (1.f - mr.w));

    reinterpret_cast<float4*>(g_xk)[idx] = ok;
    reinterpret_cast<float4*>(g_xv)[idx] = ov;
    reinterpret_cast<float4*>(g_xr)[idx] = orr;
}

// ---------------- 2. tf32 tensor-core GEMM:  C[M,N] = A[M,K] * B[N,K]^T -------
// 128x128x32 tile, 4 warps (64x64), 3-stage cp.async pipeline,
// XOR-swizzled smem + ldmatrix.x4 fragment loads.
#define SWIZ(m, k) (((m) << 5) + (((((k) >> 2) ^ ((m) & 7))) << 2) + ((k) & 3))
#define STAGE_F 8192   // floats per stage: A 128*32 + B 128*32
#define NSTAGE  3

__global__ __launch_bounds__(128, 2)
void gemm_tf32(const float* __restrict__ A, const float* __restrict__ B,
               float* __restrict__ C, int M, int N, int K, int act)
{
    extern __shared__ float sm[];
    const int tid  = threadIdx.x;
    const int lane = tid & 31;
    const int wid  = tid >> 5;
    const int wm = (wid >> 1) << 6;     // 0 or 64
    const int wn = (wid & 1) << 6;      // 0 or 64
    const int g  = lane >> 2;           // 0..7
    const int tg = lane & 3;            // 0..3

    // ---- global->smem producer mapping ----
    const int kc = tid & 7;             // 16B chunk in K (0..7)
    const int m0 = tid >> 3;            // 0..15
    const int dc = kc ^ (m0 & 7);       // swizzled chunk

    const float* Ag = A + ((((size_t)blockIdx.y) << 7) + m0) * K + (size_t)kc * 4;
    const float* Bg = B + ((((size_t)blockIdx.x) << 7) + m0) * K + (size_t)kc * 4;

    uint32_t sbase = (uint32_t)__cvta_generic_to_shared(sm);
    uint32_t dA = sbase + (uint32_t)(((m0 << 5) + (dc << 2)) << 2);
    uint32_t dB = dA + (4096u << 2);

    // ---- ldmatrix per-lane address precompute ----
    // A fragment (mi): x4 tiles = {(m,kk),(m+8,kk),(m,kk+4),(m+8,kk+4)}
    //   lane group hi = lane>>3: hi&1 -> +8 rows, hi>>1 -> +4 k
    const int hi = lane >> 3;
    const int rr = lane & 7;
    uint32_t aRowOff[4], aLow[4];
    #pragma unroll
    for (int mi = 0; mi < 4; mi++) {
        int row = wm + (mi << 4) + ((hi & 1) << 3) + rr;
        aRowOff[mi] = (uint32_t)(row << 7);          // row * 32 floats * 4B
        aLow[mi] = (uint32_t)(row & 7);
    }
    const uint32_t aHi = (uint32_t)(hi >> 1);
    // B pair (nj): x4 tiles = {(n0,kk),(n0,kk+4),(n1,kk),(n1,kk+4)}, n0=2nj*8, n1=n0+8
    //   hi>>1 -> +8 rows (odd ni), hi&1 -> +4 k
    uint32_t bRowOff[4], bLow[4];
    #pragma unroll
    for (int nj = 0; nj < 4; nj++) {
        int row = wn + (((nj << 1) + (hi >> 1)) << 3) + rr;
        bRowOff[nj] = (uint32_t)(row << 7);
        bLow[nj] = (uint32_t)(row & 7);
    }
    const uint32_t bHi = (uint32_t)(hi & 1);

    float acc[4][8][4];
    #pragma unroll
    for (int i = 0; i < 4; i++)
        #pragma unroll
        for (int j = 0; j < 8; j++)
            #pragma unroll
            for (int l = 0; l < 4; l++) acc[i][j][l] = 0.f;

    const int kIters = K >> 5;

#define ISSUE(IT, S)                                                          \
    {                                                                         \
        uint32_t offS = (uint32_t)((S) * (STAGE_F * 4));                      \
        const float* ap = Ag + (size_t)(IT) * 32;                             \
        const float* bp = Bg + (size_t)(IT) * 32;                             \
        _Pragma("unroll")                                                     \
        for (int j = 0; j < 8; j++) {                                         \
            cp_async16(dA + offS + (uint32_t)(j * 2048),                      \
                       ap + (size_t)(j << 4) * K);                            \
            cp_async16(dB + offS + (uint32_t)(j * 2048),                      \
                       bp + (size_t)(j << 4) * K);                            \
        }                                                                     \
        asm volatile("cp.async.commit_group;" ::);                            \
    }

    ISSUE(0, 0);
    if (kIters > 1) ISSUE(1, 1);

    int stage = 0;
    for (int it = 0; it < kIters; ++it) {
        if (it + 2 < kIters) {
            int s2 = it + 2; int st2 = s2 - (s2 / NSTAGE) * NSTAGE;
            ISSUE(s2, st2);
            asm volatile("cp.async.wait_group 2;" ::);
        } else if (it + 1 < kIters) {
            asm volatile("cp.async.wait_group 1;" ::);
        } else {
            asm volatile("cp.async.wait_group 0;" ::);
        }
        __syncthreads();

        uint32_t sA = sbase + (uint32_t)(stage * (STAGE_F * 4));
        uint32_t sB = sA + (4096u << 2);

        #pragma unroll
        for (int kq = 0; kq < 4; kq++) {
            const uint32_t kq2 = (uint32_t)(kq << 1);
            uint32_t af[4][4];
            #pragma unroll
            for (int mi = 0; mi < 4; mi++) {
                uint32_t addr = sA + aRowOff[mi] + (((kq2 + aHi) ^ aLow[mi]) << 4);
                ldsm_x4(af[mi][0], af[mi][1], af[mi][2], af[mi][3], addr);
            }
            #pragma unroll
            for (int nj = 0; nj < 4; nj++) {
                uint32_t q0, q1, q2, q3;
                uint32_t addr = sB + bRowOff[nj] + (((kq2 + bHi) ^ bLow[nj]) << 4);
                ldsm_x4(q0, q1, q2, q3, addr);
                #pragma unroll
                for (int mi = 0; mi < 4; mi++) {
                    mma_m16n8k8(acc[mi][nj * 2],     af[mi], q0, q1);
                    mma_m16n8k8(acc[mi][nj * 2 + 1], af[mi], q2, q3);
                }
            }
        }
        __syncthreads();
        stage = (stage + 1 == NSTAGE) ? 0 : stage + 1;
    }

    // ---- epilogue ----
    size_t rowBase = (((size_t)blockIdx.y) << 7) + wm + g;
    int colBase = (blockIdx.x << 7) + wn + (tg << 1);
    #pragma unroll
    for (int mi = 0; mi < 4; mi++) {
        #pragma unroll
        for (int ni = 0; ni < 8; ni++) {
            size_t r0 = rowBase + (mi << 4);
            int col = colBase + (ni << 3);
            float x0 = acc[mi][ni][0], x1 = acc[mi][ni][1];
            float x2 = acc[mi][ni][2], x3 = acc[mi][ni][3];
            if (act) {
                x0 = 1.f / (1.f + expf(-x0));
                x1 = 1.f / (1.f + expf(-x1));
                x2 = 1.f / (1.f + expf(-x2));
                x3 = 1.f / (1.f + expf(-x3));
            }
            *reinterpret_cast<float2*>(C + r0 * N + col)       = make_float2(x0, x1);
            *reinterpret_cast<float2*>(C + (r0 + 8) * N + col) = make_float2(x2, x3);
        }
    }
}

// ---------------- 3. wkv scan + gating ----------------------------------------
#define WKV_U 16
__global__ void wkv_kernel(const float* __restrict__ time_decay,
                           const float* __restrict__ time_first)
{
    int idx = blockIdx.x * blockDim.x + threadIdx.x;   // over BSZ*DDIM
    int b = idx / DDIM;
    int d = idx % DDIM;

    float ew = expf(-expf(time_decay[d]));
    float eu = expf(time_first[d]);

    const float* kp = g_k + (size_t)b * TLEN * DDIM + d;
    const float* vp = g_v + (size_t)b * TLEN * DDIM + d;
    const float* rp = g_r + (size_t)b * TLEN * DDIM + d;
    float*       op = g_rwkv + (size_t)b * TLEN * DDIM + d;

    float aa = 0.f, bb = 0.f;

    for (int t0 = 0; t0 < TLEN; t0 += WKV_U) {
        float kk[WKV_U], vv[WKV_U], rr[WKV_U];
        #pragma unroll
        for (int i = 0; i < WKV_U; i++) {
            kk[i] = kp[(size_t)(t0 + i) * DDIM];
            vv[i] = vp[(size_t)(t0 + i) * DDIM];
            rr[i] = rp[(size_t)(t0 + i) * DDIM];
        }
        #pragma unroll
        for (int i = 0; i < WKV_U; i++) {
            float ek  = expf(kk[i]);
            float ekv = ek * vv[i];
            float out = (eu * ekv + aa) / (eu * ek + bb);
            op[(size_t)(t0 + i) * DDIM] = tf32r(rr[i] * out);
            aa = ew * aa + ekv;
            bb = ew * bb + ek;
        }
    }
}

// ---------------- launch ------------------------------------------------------
extern "C" void kernel_launch(void* const* d_in, const int* in_sizes, int n_in,
                              void* d_out, int out_size)
{
    const float* x    = (const float*)d_in[0];
    const float* td   = (const float*)d_in[1];
    const float* tf   = (const float*)d_in[2];
    const float* tmk  = (const float*)d_in[3];
    const float* tmv  = (const float*)d_in[4];
    const float* tmr  = (const float*)d_in[5];
    const float* Wk   = (const float*)d_in[6];
    const float* Wv   = (const float*)d_in[7];
    const float* Wr   = (const float*)d_in[8];
    const float* Wo   = (const float*)d_in[9];
    float* out = (float*)d_out;

    float *p_xk, *p_xv, *p_xr, *p_k, *p_v, *p_r, *p_rwkv;
    float *p_Wk, *p_Wv, *p_Wr, *p_Wo;
    cudaGetSymbolAddress((void**)&p_xk, g_xk);
    cudaGetSymbolAddress((void**)&p_xv, g_xv);
    cudaGetSymbolAddress((void**)&p_xr, g_xr);
    cudaGetSymbolAddress((void**)&p_k,  g_k);
    cudaGetSymbolAddress((void**)&p_v,  g_v);
    cudaGetSymbolAddress((void**)&p_r,  g_r);
    cudaGetSymbolAddress((void**)&p_rwkv, g_rwkv);
    cudaGetSymbolAddress((void**)&p_Wk, g_Wk);
    cudaGetSymbolAddress((void**)&p_Wv, g_Wv);
    cudaGetSymbolAddress((void**)&p_Wr, g_Wr);
    cudaGetSymbolAddress((void**)&p_Wo, g_Wo);

    size_t smem = (size_t)NSTAGE * STAGE_F * 4;
    cudaFuncSetAttribute(gemm_tf32, cudaFuncAttributeMaxDynamicSharedMemorySize,
                         (int)smem);

    // 0. round all weights to tf32 (single launch)
    {
        int n4 = 4 * (DDIM * CDIM) / 4;
        round_weights<<<n4 / 256, 256>>>(Wk, Wv, Wr, Wo);
    }

    // 1. mixing (tf32-rounded outputs)
    {
        int n = MTOT * CDIM / 4;
        mix_kernel<<<n / 256, 256>>>(x, tmk, tmv, tmr);
    }

    // 2. projections on tensor cores
    dim3 grid(DDIM / 128, MTOT / 128);
    gemm_tf32<<<grid, 128, smem>>>(p_xk, p_Wk, p_k, MTOT, DDIM, CDIM, 0);
    gemm_tf32<<<grid, 128, smem>>>(p_xv, p_Wv, p_v, MTOT, DDIM, CDIM, 0);
    gemm_tf32<<<grid, 128, smem>>>(p_xr, p_Wr, p_r, MTOT, DDIM, CDIM, 1);

    // 3. wkv scan (+ gate by sigmoid(r))
    wkv_kernel<<<(BSZ * DDIM) / 64, 64>>>(td, tf);

    // 4. output projection
    dim3 grid2(CDIM / 128, MTOT / 128);
    gemm_tf32<<<grid2, 128, smem>>>(p_rwkv, p_Wo, out, MTOT, CDIM, DDIM, 0);
}